// round 15
// baseline (speedup 1.0000x reference)
#include <cuda_runtime.h>
#include <math.h>

#define G        512
#define S        32
#define PTS      8
#define SEGS_PER (PTS - 1)           // 7
#define NSEG     (S * SEGS_PER)      // 224
#define TILE     16
#define NTHREADS 128                 // 8 thread-cols x 16 rows, 2 px/thread
#define TPR      (G / TILE)          // 32 tiles per row

__device__ __forceinline__ float fast_sqrt(float x) {
    float r;
    asm("sqrt.approx.f32 %0, %1;" : "=f"(r) : "f"(x));
    return r;
}

// ---------------------------------------------------------------------------
// FINAL KERNEL (session-converged configuration).
// One 16x16 tile per 128-thread CTA (1024 CTAs, single wave, ~28 warps/SM).
// Cull: 224 segments in 2 warp-uniform rounds (128 + 96). Each thread loads
//   its segment's points + thickness straight from global (issued before the
//   first barrier so latency hides under it), capsule-culls vs tile center
//   (any segment farther than 2t + tile half-diagonal + margin contributes
//   darkness >= 1 and is dropped), then warp-ballot compacts survivors
//   (one shared atomicAdd per warp per round).
//   Survivor record: (vx,vy,ex,ey) + (fx,fy,sc,-) with fx,fy = e*invd2 and
//   sc = 1/(4t^2), so render-time frac needs no divide or extra multiply
//   and min over segments/strokes is taken on scaled SQUARED distance
//   (sqrt is monotone -> one sqrt per pixel at the very end).
// Render: 2 horizontally adjacent pixels per thread sharing dx and dx*fx;
//   two independent min chains; MUFU sqrt.approx epilogue; float2 store.
// ---------------------------------------------------------------------------
__global__ void __launch_bounds__(NTHREADS)
render_kernel(const float* __restrict__ strokes,
              const float* __restrict__ thick,
              float* __restrict__ out) {
    __shared__ float4 s_a[NSEG];     // vx, vy, ex, ey
    __shared__ float4 s_b[NSEG];     // fx, fy, sc, pad
    __shared__ int    s_n;

    const int tid  = threadIdx.x;
    const int lane = tid & 31;
    const int wid  = tid >> 5;

    // ---- Issue segment loads early (latency hides under the first barrier) ----
    int    s0 = (tid * 9363) >> 16;                // tid / 7
    int    i0 = s0 * PTS + (tid - s0 * SEGS_PER);  // point index
    float2 a0 = ((const float2*)strokes)[i0];
    float2 b0 = ((const float2*)strokes)[i0 + 1];
    float  t0 = thick[s0];

    int    seg1 = 128 + tid;
    float2 a1 = make_float2(0.f, 0.f), b1 = a1;
    float  t1 = 0.f;
    if (wid < 3) {                                 // seg1 in [128, 224)
        int s1 = (seg1 * 9363) >> 16;
        int i1 = s1 * PTS + (seg1 - s1 * SEGS_PER);
        a1 = ((const float2*)strokes)[i1];
        b1 = ((const float2*)strokes)[i1 + 1];
        t1 = thick[s1];
    }

    if (tid == 0) s_n = 0;
    __syncthreads();

    const int ti = blockIdx.y * TILE;              // row base (out stride G)
    const int tj = blockIdx.x * TILE;              // col base (contiguous)

    const float cx   = (float)ti + (TILE - 1) * 0.5f;
    const float cy   = (float)tj + (TILE - 1) * 0.5f;
    const float RMAX = (TILE - 1) * 0.5f * 1.41421356f + 1.0f;

    // ---- Cull round helper (inlined twice) ----
    #define CULL_ROUND(P0, P1, TK)                                            \
    {                                                                         \
        float vx = __saturatef((P0).x) * (float)G;                            \
        float vy = __saturatef((P0).y) * (float)G;                            \
        float wx = __saturatef((P1).x) * (float)G;                            \
        float wy = __saturatef((P1).y) * (float)G;                            \
        float ex = wx - vx;                                                   \
        float ey = wy - vy;                                                   \
        float d2 = ex * ex + ey * ey;                                         \
        float invd2 = __fdividef(1.0f, d2 + 1e-5f);                           \
        float t  = fmaxf(fmaf((TK), 2.0f, 0.5f), 0.5f);                       \
        float r  = 2.0f * t;                                                  \
        float dx  = cx - vx;                                                  \
        float dy  = cy - vy;                                                  \
        float dot = dx * ex + dy * ey;                                        \
        float fr  = __saturatef(dot * invd2);                                 \
        float ddx = fmaf(-fr, ex, dx);                                        \
        float ddy = fmaf(-fr, ey, dy);                                        \
        float dq  = ddx * ddx + ddy * ddy;                                    \
        float thr = r + RMAX;                                                 \
        bool keep = (dq <= thr * thr);                                        \
        unsigned bal = __ballot_sync(0xffffffffu, keep);                      \
        int base = 0;                                                         \
        if (lane == 0 && bal) base = atomicAdd(&s_n, __popc(bal));            \
        base = __shfl_sync(0xffffffffu, base, 0);                             \
        if (keep) {                                                           \
            int p = base + __popc(bal & ((1u << lane) - 1u));                 \
            s_a[p] = make_float4(vx, vy, ex, ey);                             \
            s_b[p] = make_float4(ex * invd2, ey * invd2,                      \
                                 __fdividef(1.0f, r * r), 0.0f);              \
        }                                                                     \
    }

    CULL_ROUND(a0, b0, t0);
    if (wid < 3) CULL_ROUND(a1, b1, t1);
    #undef CULL_ROUND

    __syncthreads();

    // ---- Render: 2 horizontally adjacent pixels per thread ----
    const int tx = tid & 7;                        // px cols 2tx, 2tx+1
    const int ty = tid >> 3;                       // row 0..15
    const float px  = (float)(ti + ty);            // row coord (meshgrid 'ij')
    const float py0 = (float)(tj + 2 * tx);        // col coord
    const int n = s_n;

    float m0 = 1e30f;
    float m1 = 1e30f;
    #pragma unroll 2
    for (int q = 0; q < n; q++) {
        float4 a = s_a[q];                         // vx vy ex ey
        float4 b = s_b[q];                         // fx fy sc -
        float dx   = px - a.x;
        float dy0  = py0 - a.y;
        float dy1  = dy0 + 1.0f;
        float dxfx = dx * b.x;
        float fr0  = __saturatef(fmaf(dy0, b.y, dxfx));
        float fr1  = __saturatef(fmaf(dy1, b.y, dxfx));
        float ddx0 = fmaf(-fr0, a.z, dx);
        float ddy0 = fmaf(-fr0, a.w, dy0);
        float ddx1 = fmaf(-fr1, a.z, dx);
        float ddy1 = fmaf(-fr1, a.w, dy1);
        float dq0  = fmaf(ddx0, ddx0, ddy0 * ddy0);
        float dq1  = fmaf(ddx1, ddx1, ddy1 * ddy1);
        m0 = fminf(m0, dq0 * b.z);
        m1 = fminf(m1, dq1 * b.z);
    }

    float2 res = make_float2(fminf(fast_sqrt(m0), 1.0f),
                             fminf(fast_sqrt(m1), 1.0f));
    *(float2*)(out + (ti + ty) * G + (tj + 2 * tx)) = res;
}

extern "C" void kernel_launch(void* const* d_in, const int* in_sizes, int n_in,
                              void* d_out, int out_size) {
    // metadata order: strokes [32,8,2] f32 (512 elems), thicknesses [32] f32.
    const float* strokes = (const float*)d_in[0];
    const float* thick   = (const float*)d_in[1];
    if (n_in >= 2 && in_sizes[0] == S && in_sizes[1] == S * PTS * 2) {
        strokes = (const float*)d_in[1];
        thick   = (const float*)d_in[0];
    }
    float* out = (float*)d_out;

    dim3 block(NTHREADS);
    dim3 grid(TPR, TPR);
    render_kernel<<<grid, block>>>(strokes, thick, out);
}

// round 16
// speedup vs baseline: 3.9227x; 3.9227x over previous
#include <cuda_runtime.h>
#include <math.h>

#define G        512
#define S        32
#define PTS      8
#define SEGS_PER (PTS - 1)           // 7
#define NSEG     (S * SEGS_PER)      // 224
#define TILE     16
#define NTHREADS 128                 // 8 thread-cols x 16 rows, 2 px/thread
#define TPR      (G / TILE)          // 32 tiles per row

__device__ __forceinline__ float fast_sqrt(float x) {
    float r;
    asm("sqrt.approx.f32 %0, %1;" : "=f"(r) : "f"(x));
    return r;
}

// ---------------------------------------------------------------------------
// FINAL KERNEL (session-converged configuration; resubmitted unchanged to
// re-measure after an inconsistent harness timing outlier in R15).
// One 16x16 tile per 128-thread CTA (1024 CTAs, single wave, ~28 warps/SM).
// Cull: 224 segments in 2 warp-uniform rounds (128 + 96). Each thread loads
//   its segment's points + thickness straight from global (issued before the
//   first barrier so latency hides under it), capsule-culls vs tile center
//   (any segment farther than 2t + tile half-diagonal + margin contributes
//   darkness >= 1 and is dropped), then warp-ballot compacts survivors
//   (one shared atomicAdd per warp per round).
//   Survivor record: (vx,vy,ex,ey) + (fx,fy,sc,-) with fx,fy = e*invd2 and
//   sc = 1/(4t^2), so render-time frac needs no divide or extra multiply
//   and min over segments/strokes is taken on scaled SQUARED distance
//   (sqrt is monotone -> one sqrt per pixel at the very end).
// Render: 2 horizontally adjacent pixels per thread sharing dx and dx*fx;
//   two independent min chains; MUFU sqrt.approx epilogue; float2 store.
// ---------------------------------------------------------------------------
__global__ void __launch_bounds__(NTHREADS)
render_kernel(const float* __restrict__ strokes,
              const float* __restrict__ thick,
              float* __restrict__ out) {
    __shared__ float4 s_a[NSEG];     // vx, vy, ex, ey
    __shared__ float4 s_b[NSEG];     // fx, fy, sc, pad
    __shared__ int    s_n;

    const int tid  = threadIdx.x;
    const int lane = tid & 31;
    const int wid  = tid >> 5;

    // ---- Issue segment loads early (latency hides under the first barrier) ----
    int    s0 = (tid * 9363) >> 16;                // tid / 7
    int    i0 = s0 * PTS + (tid - s0 * SEGS_PER);  // point index
    float2 a0 = ((const float2*)strokes)[i0];
    float2 b0 = ((const float2*)strokes)[i0 + 1];
    float  t0 = thick[s0];

    int    seg1 = 128 + tid;
    float2 a1 = make_float2(0.f, 0.f), b1 = a1;
    float  t1 = 0.f;
    if (wid < 3) {                                 // seg1 in [128, 224)
        int s1 = (seg1 * 9363) >> 16;
        int i1 = s1 * PTS + (seg1 - s1 * SEGS_PER);
        a1 = ((const float2*)strokes)[i1];
        b1 = ((const float2*)strokes)[i1 + 1];
        t1 = thick[s1];
    }

    if (tid == 0) s_n = 0;
    __syncthreads();

    const int ti = blockIdx.y * TILE;              // row base (out stride G)
    const int tj = blockIdx.x * TILE;              // col base (contiguous)

    const float cx   = (float)ti + (TILE - 1) * 0.5f;
    const float cy   = (float)tj + (TILE - 1) * 0.5f;
    const float RMAX = (TILE - 1) * 0.5f * 1.41421356f + 1.0f;

    // ---- Cull round helper (inlined twice) ----
    #define CULL_ROUND(P0, P1, TK)                                            \
    {                                                                         \
        float vx = __saturatef((P0).x) * (float)G;                            \
        float vy = __saturatef((P0).y) * (float)G;                            \
        float wx = __saturatef((P1).x) * (float)G;                            \
        float wy = __saturatef((P1).y) * (float)G;                            \
        float ex = wx - vx;                                                   \
        float ey = wy - vy;                                                   \
        float d2 = ex * ex + ey * ey;                                         \
        float invd2 = __fdividef(1.0f, d2 + 1e-5f);                           \
        float t  = fmaxf(fmaf((TK), 2.0f, 0.5f), 0.5f);                       \
        float r  = 2.0f * t;                                                  \
        float dx  = cx - vx;                                                  \
        float dy  = cy - vy;                                                  \
        float dot = dx * ex + dy * ey;                                        \
        float fr  = __saturatef(dot * invd2);                                 \
        float ddx = fmaf(-fr, ex, dx);                                        \
        float ddy = fmaf(-fr, ey, dy);                                        \
        float dq  = ddx * ddx + ddy * ddy;                                    \
        float thr = r + RMAX;                                                 \
        bool keep = (dq <= thr * thr);                                        \
        unsigned bal = __ballot_sync(0xffffffffu, keep);                      \
        int base = 0;                                                         \
        if (lane == 0 && bal) base = atomicAdd(&s_n, __popc(bal));            \
        base = __shfl_sync(0xffffffffu, base, 0);                             \
        if (keep) {                                                           \
            int p = base + __popc(bal & ((1u << lane) - 1u));                 \
            s_a[p] = make_float4(vx, vy, ex, ey);                             \
            s_b[p] = make_float4(ex * invd2, ey * invd2,                      \
                                 __fdividef(1.0f, r * r), 0.0f);              \
        }                                                                     \
    }

    CULL_ROUND(a0, b0, t0);
    if (wid < 3) CULL_ROUND(a1, b1, t1);
    #undef CULL_ROUND

    __syncthreads();

    // ---- Render: 2 horizontally adjacent pixels per thread ----
    const int tx = tid & 7;                        // px cols 2tx, 2tx+1
    const int ty = tid >> 3;                       // row 0..15
    const float px  = (float)(ti + ty);            // row coord (meshgrid 'ij')
    const float py0 = (float)(tj + 2 * tx);        // col coord
    const int n = s_n;

    float m0 = 1e30f;
    float m1 = 1e30f;
    #pragma unroll 2
    for (int q = 0; q < n; q++) {
        float4 a = s_a[q];                         // vx vy ex ey
        float4 b = s_b[q];                         // fx fy sc -
        float dx   = px - a.x;
        float dy0  = py0 - a.y;
        float dy1  = dy0 + 1.0f;
        float dxfx = dx * b.x;
        float fr0  = __saturatef(fmaf(dy0, b.y, dxfx));
        float fr1  = __saturatef(fmaf(dy1, b.y, dxfx));
        float ddx0 = fmaf(-fr0, a.z, dx);
        float ddy0 = fmaf(-fr0, a.w, dy0);
        float ddx1 = fmaf(-fr1, a.z, dx);
        float ddy1 = fmaf(-fr1, a.w, dy1);
        float dq0  = fmaf(ddx0, ddx0, ddy0 * ddy0);
        float dq1  = fmaf(ddx1, ddx1, ddy1 * ddy1);
        m0 = fminf(m0, dq0 * b.z);
        m1 = fminf(m1, dq1 * b.z);
    }

    float2 res = make_float2(fminf(fast_sqrt(m0), 1.0f),
                             fminf(fast_sqrt(m1), 1.0f));
    *(float2*)(out + (ti + ty) * G + (tj + 2 * tx)) = res;
}

extern "C" void kernel_launch(void* const* d_in, const int* in_sizes, int n_in,
                              void* d_out, int out_size) {
    // metadata order: strokes [32,8,2] f32 (512 elems), thicknesses [32] f32.
    const float* strokes = (const float*)d_in[0];
    const float* thick   = (const float*)d_in[1];
    if (n_in >= 2 && in_sizes[0] == S && in_sizes[1] == S * PTS * 2) {
        strokes = (const float*)d_in[1];
        thick   = (const float*)d_in[0];
    }
    float* out = (float*)d_out;

    dim3 block(NTHREADS);
    dim3 grid(TPR, TPR);
    render_kernel<<<grid, block>>>(strokes, thick, out);
}